// round 6
// baseline (speedup 1.0000x reference)
#include <cuda_runtime.h>
#include <math.h>

#define DM   4096
#define LD   512
#define BB   4
#define SP   4096
#define STOT 4097
#define CHUNK 8
#define NCHUNK 513   /* ceil(4097/8) */

// -------------------- device scratch (no allocs allowed) --------------------
__device__ float g_Cq[BB * DM];
__device__ float g_Qc[BB * DM];
__device__ float g_Qr[BB * DM];
__device__ float g_u [BB * LD];
__device__ float g_t [BB * DM];                 // scale*(Wkr@Qr + Wdkv@u)
__device__ float g_m [BB * NCHUNK];
__device__ float g_l [BB * NCHUNK];
__device__ float g_acc[(size_t)BB * NCHUNK * DM];  // 33.6 MB flash partials
__device__ float g_p [BB * DM];
__device__ float g_a [BB * LD];
__device__ float g_av[BB * DM];

// -------------------- zero the atomic-accumulated buffers -------------------
__global__ void k_zero(float* __restrict__ out) {
    int i = blockIdx.x * blockDim.x + threadIdx.x;
    int stride = gridDim.x * blockDim.x;
    for (int j = i; j < BB * DM; j += stride) {
        g_Cq[j] = 0.f; g_Qc[j] = 0.f; g_Qr[j] = 0.f; g_av[j] = 0.f; out[j] = 0.f;
    }
    for (int j = i; j < BB * LD; j += stride) g_a[j] = 0.f;
}

__device__ __forceinline__ void fma4(float4& acc, float s, const float4& v) {
    acc.x += s * v.x; acc.y += s * v.y; acc.z += s * v.z; acc.w += s * v.w;
}

// ---- Y[b][:] += X[b][:] @ W   (float4 columns, split-K, unroll-16 MLP) -----
__global__ __launch_bounds__(256) void k_gemv4(
    const float* __restrict__ X, int xstride,
    const float* __restrict__ W0, const float* __restrict__ W1, int ldw,
    float* __restrict__ Y0, float* __restrict__ Y1, int ystride,
    int K, int N, int kchunk)
{
    const float* W = blockIdx.z ? W1 : W0;
    float*       Y = blockIdx.z ? Y1 : Y0;
    const int N4 = N >> 2;
    const int ldw4 = ldw >> 2;
    int tid = threadIdx.x;
    int j4  = blockIdx.x * blockDim.x + tid;
    int d0  = blockIdx.y * kchunk;
    int d1  = min(K, d0 + kchunk);
    int nk  = d1 - d0;

    __shared__ float sx[BB][64];   // kchunk <= 64
    for (int i = tid; i < BB * nk; i += blockDim.x) {
        int bb = i / nk, kk = i - bb * nk;
        sx[bb][kk] = X[bb * xstride + d0 + kk];
    }
    __syncthreads();
    if (j4 >= N4) return;

    const float4* W4 = reinterpret_cast<const float4*>(W);
    float4 a0 = {0,0,0,0}, a1 = a0, a2 = a0, a3 = a0;

    int k = 0;
    for (; k + 16 <= nk; k += 16) {
        float4 wv[16];
        #pragma unroll
        for (int i = 0; i < 16; i++)
            wv[i] = W4[(size_t)(d0 + k + i) * ldw4 + j4];
        #pragma unroll
        for (int i = 0; i < 16; i++) {
            fma4(a0, sx[0][k + i], wv[i]);
            fma4(a1, sx[1][k + i], wv[i]);
            fma4(a2, sx[2][k + i], wv[i]);
            fma4(a3, sx[3][k + i], wv[i]);
        }
    }
    for (; k < nk; k++) {
        float4 wv = W4[(size_t)(d0 + k) * ldw4 + j4];
        fma4(a0, sx[0][k], wv); fma4(a1, sx[1][k], wv);
        fma4(a2, sx[2][k], wv); fma4(a3, sx[3][k], wv);
    }

    int j = j4 * 4;
    atomicAdd(&Y[0 * ystride + j + 0], a0.x); atomicAdd(&Y[0 * ystride + j + 1], a0.y);
    atomicAdd(&Y[0 * ystride + j + 2], a0.z); atomicAdd(&Y[0 * ystride + j + 3], a0.w);
    atomicAdd(&Y[1 * ystride + j + 0], a1.x); atomicAdd(&Y[1 * ystride + j + 1], a1.y);
    atomicAdd(&Y[1 * ystride + j + 2], a1.z); atomicAdd(&Y[1 * ystride + j + 3], a1.w);
    atomicAdd(&Y[2 * ystride + j + 0], a2.x); atomicAdd(&Y[2 * ystride + j + 1], a2.y);
    atomicAdd(&Y[2 * ystride + j + 2], a2.z); atomicAdd(&Y[2 * ystride + j + 3], a2.w);
    atomicAdd(&Y[3 * ystride + j + 0], a3.x); atomicAdd(&Y[3 * ystride + j + 1], a3.y);
    atomicAdd(&Y[3 * ystride + j + 2], a3.z); atomicAdd(&Y[3 * ystride + j + 3], a3.w);
}

// ---- y[b][r] = sum_c W[r][c] * X[b][c]   (warp/row, X staged in smem) ------
// X must be [BB, cols] contiguous. Dynamic smem = BB*cols*4 bytes.
__global__ __launch_bounds__(256) void k_gemv_t(
    const float* __restrict__ X,
    const float* __restrict__ W, int ldw,
    float* __restrict__ Y, int ystride,
    int rows, int cols, int accum_scale, float scalev)
{
    extern __shared__ float sxs[];
    float4* sx4 = reinterpret_cast<float4*>(sxs);
    int tid  = threadIdx.x;
    int cols4 = cols >> 2;

    const float4* X4g = reinterpret_cast<const float4*>(X);
    for (int i = tid; i < BB * cols4; i += 256) sx4[i] = X4g[i];
    __syncthreads();

    int wid  = tid >> 5;
    int lane = tid & 31;
    int gw   = blockIdx.x * 8 + wid;
    if (gw >= rows) return;

    const float4* wp = reinterpret_cast<const float4*>(W + (size_t)gw * ldw);
    float4 a0 = {0,0,0,0}, a1 = a0, a2 = a0, a3 = a0;

    int cb = 0;
    for (; cb + 256 <= cols4; cb += 256) {
        float4 wv[8];
        #pragma unroll
        for (int i = 0; i < 8; i++) wv[i] = __ldg(&wp[cb + lane + 32 * i]);
        #pragma unroll
        for (int i = 0; i < 8; i++) {
            int c4 = cb + lane + 32 * i;
            float4 x0 = sx4[c4];
            float4 x1 = sx4[cols4 + c4];
            float4 x2 = sx4[2 * cols4 + c4];
            float4 x3 = sx4[3 * cols4 + c4];
            a0.x += wv[i].x * x0.x; a0.y += wv[i].y * x0.y; a0.z += wv[i].z * x0.z; a0.w += wv[i].w * x0.w;
            a1.x += wv[i].x * x1.x; a1.y += wv[i].y * x1.y; a1.z += wv[i].z * x1.z; a1.w += wv[i].w * x1.w;
            a2.x += wv[i].x * x2.x; a2.y += wv[i].y * x2.y; a2.z += wv[i].z * x2.z; a2.w += wv[i].w * x2.w;
            a3.x += wv[i].x * x3.x; a3.y += wv[i].y * x3.y; a3.z += wv[i].z * x3.z; a3.w += wv[i].w * x3.w;
        }
    }
    #pragma unroll 4
    for (int c4 = cb + lane; c4 < cols4; c4 += 32) {
        float4 wv = __ldg(&wp[c4]);
        float4 x0 = sx4[c4];
        float4 x1 = sx4[cols4 + c4];
        float4 x2 = sx4[2 * cols4 + c4];
        float4 x3 = sx4[3 * cols4 + c4];
        a0.x += wv.x * x0.x; a0.y += wv.y * x0.y; a0.z += wv.z * x0.z; a0.w += wv.w * x0.w;
        a1.x += wv.x * x1.x; a1.y += wv.y * x1.y; a1.z += wv.z * x1.z; a1.w += wv.w * x1.w;
        a2.x += wv.x * x2.x; a2.y += wv.y * x2.y; a2.z += wv.z * x2.z; a2.w += wv.w * x2.w;
        a3.x += wv.x * x3.x; a3.y += wv.y * x3.y; a3.z += wv.z * x3.z; a3.w += wv.w * x3.w;
    }

    float s0 = a0.x + a0.y + a0.z + a0.w;
    float s1 = a1.x + a1.y + a1.z + a1.w;
    float s2 = a2.x + a2.y + a2.z + a2.w;
    float s3 = a3.x + a3.y + a3.z + a3.w;
    #pragma unroll
    for (int o = 16; o > 0; o >>= 1) {
        s0 += __shfl_xor_sync(0xffffffffu, s0, o);
        s1 += __shfl_xor_sync(0xffffffffu, s1, o);
        s2 += __shfl_xor_sync(0xffffffffu, s2, o);
        s3 += __shfl_xor_sync(0xffffffffu, s3, o);
    }
    if (lane == 0) {
        if (accum_scale) {
            Y[0 * ystride + gw] = scalev * (Y[0 * ystride + gw] + s0);
            Y[1 * ystride + gw] = scalev * (Y[1 * ystride + gw] + s1);
            Y[2 * ystride + gw] = scalev * (Y[2 * ystride + gw] + s2);
            Y[3 * ystride + gw] = scalev * (Y[3 * ystride + gw] + s3);
        } else {
            Y[0 * ystride + gw] = s0;
            Y[1 * ystride + gw] = s1;
            Y[2 * ystride + gw] = s2;
            Y[3 * ystride + gw] = s3;
        }
    }
}

// ---- flash pass, two-phase: barrier-free score streaming, then weighted sum
__global__ __launch_bounds__(256) void k_flash(
    const float* __restrict__ x, const float* __restrict__ past)
{
    int b    = blockIdx.y;
    int c    = blockIdx.x;
    int tid  = threadIdx.x;
    int wid  = tid >> 5;
    int lane = tid & 31;
    __shared__ float sred[CHUNK * 8];

    const float4* t4 = reinterpret_cast<const float4*>(g_t + (size_t)b * DM);
    float4 t0 = t4[tid], t1 = t4[tid + 256], t2 = t4[tid + 512], t3 = t4[tid + 768];

    int s0 = c * CHUNK;

    // ---- phase 1: partial dots for all CHUNK rows, no barriers ----
    float p[CHUNK];
    #pragma unroll
    for (int i = 0; i < CHUNK; i++) {
        int sc = min(s0 + i, STOT - 1);
        const float4* rp = reinterpret_cast<const float4*>(
            (sc < SP) ? past + ((size_t)b * SP + sc) * DM : x + (size_t)b * DM);
        float4 v0 = rp[tid], v1 = rp[tid + 256], v2 = rp[tid + 512], v3 = rp[tid + 768];
        p[i] = v0.x*t0.x + v0.y*t0.y + v0.z*t0.z + v0.w*t0.w
             + v1.x*t1.x + v1.y*t1.y + v1.z*t1.z + v1.w*t1.w
             + v2.x*t2.x + v2.y*t2.y + v2.z*t2.z + v2.w*t2.w
             + v3.x*t3.x + v3.y*t3.y + v3.z*t3.z + v3.w*t3.w;
    }
    #pragma unroll
    for (int i = 0; i < CHUNK; i++) {
        float v = p[i];
        #pragma unroll
        for (int o = 16; o > 0; o >>= 1) v += __shfl_xor_sync(0xffffffffu, v, o);
        if (lane == 0) sred[i * 8 + wid] = v;
    }
    __syncthreads();

    // ---- chunk-local softmax weights (computed redundantly by all threads) --
    float score[CHUNK];
    float m = -INFINITY;
    #pragma unroll
    for (int i = 0; i < CHUNK; i++) {
        float s = 0.f;
        #pragma unroll
        for (int w = 0; w < 8; w++) s += sred[i * 8 + w];
        score[i] = (s0 + i < STOT) ? s : -INFINITY;
        m = fmaxf(m, score[i]);
    }
    float e[CHUNK];
    float l = 0.f;
    #pragma unroll
    for (int i = 0; i < CHUNK; i++) {
        e[i] = (s0 + i < STOT) ? __expf(score[i] - m) : 0.f;
        l += e[i];
    }

    // ---- phase 2: weighted row accumulation (rows hot in L1/L2), no barriers
    float4 A0 = {0,0,0,0}, A1 = A0, A2 = A0, A3 = A0;
    #pragma unroll
    for (int i = 0; i < CHUNK; i++) {
        int sc = min(s0 + i, STOT - 1);
        const float4* rp = reinterpret_cast<const float4*>(
            (sc < SP) ? past + ((size_t)b * SP + sc) * DM : x + (size_t)b * DM);
        float4 v0 = rp[tid], v1 = rp[tid + 256], v2 = rp[tid + 512], v3 = rp[tid + 768];
        fma4(A0, e[i], v0); fma4(A1, e[i], v1);
        fma4(A2, e[i], v2); fma4(A3, e[i], v3);
    }

    float4* acc4 = reinterpret_cast<float4*>(g_acc + ((size_t)b * NCHUNK + c) * DM);
    acc4[tid] = A0; acc4[tid + 256] = A1; acc4[tid + 512] = A2; acc4[tid + 768] = A3;
    if (tid == 0) { g_m[b * NCHUNK + c] = m; g_l[b * NCHUNK + c] = l; }
}

// ---- combine chunk partials -> p[b][d] (stats recomputed per block) --------
__global__ __launch_bounds__(256) void k_combine() {
    int b   = blockIdx.y;
    int tid = threadIdx.x;
    __shared__ float swc[NCHUNK];
    __shared__ float sr[8];
    __shared__ float sM, sLinv;

    float m = -INFINITY;
    for (int c = tid; c < NCHUNK; c += 256) m = fmaxf(m, g_m[b * NCHUNK + c]);
    #pragma unroll
    for (int o = 16; o > 0; o >>= 1) m = fmaxf(m, __shfl_xor_sync(0xffffffffu, m, o));
    if ((tid & 31) == 0) sr[tid >> 5] = m;
    __syncthreads();
    if (tid < 8) {
        float v = sr[tid];
        #pragma unroll
        for (int o = 4; o > 0; o >>= 1) v = fmaxf(v, __shfl_xor_sync(0xffu, v, o));
        if (tid == 0) sM = v;
    }
    __syncthreads();
    float M = sM;

    float lsum = 0.f;
    for (int c = tid; c < NCHUNK; c += 256) {
        float w = __expf(g_m[b * NCHUNK + c] - M);
        swc[c] = w;
        lsum += w * g_l[b * NCHUNK + c];
    }
    __syncthreads();   // all reads of sr (max phase) done before rewrite
    #pragma unroll
    for (int o = 16; o > 0; o >>= 1) lsum += __shfl_xor_sync(0xffffffffu, lsum, o);
    if ((tid & 31) == 0) sr[tid >> 5] = lsum;
    __syncthreads();
    if (tid == 0) {
        float L = 0.f;
        #pragma unroll
        for (int w = 0; w < 8; w++) L += sr[w];
        sLinv = 1.f / L;
    }
    __syncthreads();

    int d = blockIdx.x * 256 + tid;
    const float* accp = g_acc + (size_t)b * NCHUNK * DM + d;
    float s = 0.f;
    #pragma unroll 4
    for (int c = 0; c < NCHUNK; c++) s += swc[c] * accp[(size_t)c * DM];
    g_p[b * DM + d] = s * sLinv;
}

// ----------------------------------------------------------------------------
extern "C" void kernel_launch(void* const* d_in, const int* in_sizes, int n_in,
                              void* d_out, int out_size)
{
    const float* x    = (const float*)d_in[0];
    const float* past = (const float*)d_in[1];
    const float* Wdq  = (const float*)d_in[2];
    const float* Wuq  = (const float*)d_in[3];
    const float* Wqr  = (const float*)d_in[4];
    const float* Wdkv = (const float*)d_in[5];
    const float* Wkr  = (const float*)d_in[6];
    const float* F    = (const float*)d_in[7];   // [LD, 2*DM]
    const float* Wo   = (const float*)d_in[8];
    float* out = (float*)d_out;

    const float scale = 1.0f / sqrtf(2.0f * (float)DM);

    float *pCq, *pQc, *pQr, *pu, *pt, *pp, *pa, *pav;
    cudaGetSymbolAddress((void**)&pCq, g_Cq);
    cudaGetSymbolAddress((void**)&pQc, g_Qc);
    cudaGetSymbolAddress((void**)&pQr, g_Qr);
    cudaGetSymbolAddress((void**)&pu,  g_u);
    cudaGetSymbolAddress((void**)&pt,  g_t);
    cudaGetSymbolAddress((void**)&pp,  g_p);
    cudaGetSymbolAddress((void**)&pa,  g_a);
    cudaGetSymbolAddress((void**)&pav, g_av);

    // Idempotent, every call (no static guards allowed).
    cudaFuncSetAttribute(k_gemv_t, cudaFuncAttributeMaxDynamicSharedMemorySize,
                         BB * DM * (int)sizeof(float));

    // 1) zero atomic targets
    k_zero<<<128, 256>>>(out);

    // 2) Cq = x @ Wdq                       [B,DM]  (64 MB)
    k_gemv4<<<dim3(4, 64, 1), 256>>>(x, DM, Wdq, Wdq, DM, pCq, pCq, DM, DM, DM, 64);
    // 3+4) Qc = Cq @ Wuq ; Qr = Cq @ Wqr    (merged, 128 MB)
    k_gemv4<<<dim3(4, 64, 2), 256>>>(pCq, DM, Wuq, Wqr, DM, pQc, pQr, DM, DM, DM, 64);
    // 5) t = Wkr @ Qr                       (64 MB)
    k_gemv_t<<<512, 256, BB * DM * sizeof(float)>>>(pQr, Wkr, DM, pt, DM, DM, DM, 0, 0.f);
    // 6) u = F[:, :DM] @ Qc                 (8 MB)
    k_gemv_t<<<64, 256, BB * DM * sizeof(float)>>>(pQc, F, 2 * DM, pu, LD, LD, DM, 0, 0.f);
    // 7) t = scale * (t + Wdkv @ u)         (8 MB)
    k_gemv_t<<<512, 256, BB * LD * sizeof(float)>>>(pu, Wdkv, LD, pt, DM, DM, LD, 1, scale);

    // 8) flash pass over [past_x; x]        (268 MB)
    k_flash<<<dim3(NCHUNK, BB), 256>>>(x, past);
    // 9) combine (+stats) -> p[b][d]
    k_combine<<<dim3(16, BB), 256>>>();

    // 10) a = p @ Wdkv                      (8 MB)
    k_gemv4<<<dim3(1, 64, 1), 256>>>(pp, DM, Wdkv, Wdkv, LD, pa, pa, LD, DM, LD, 64);
    // 11) attn_v = a @ F[:, DM:]            (8 MB)
    k_gemv4<<<dim3(4, 8, 1), 256>>>(pa, LD, F + DM, F + DM, 2 * DM, pav, pav, DM, LD, DM, 64);
    // 12) out = attn_v @ Wo                 (64 MB)
    k_gemv4<<<dim3(4, 64, 1), 256>>>(pav, DM, Wo, Wo, DM, out, out, DM, DM, DM, 64);
}

// round 8
// speedup vs baseline: 1.3511x; 1.3511x over previous
#include <cuda_runtime.h>
#include <math.h>
#include <stdint.h>

#define DM    4096
#define LD    512
#define BB    4
#define SP    4096
#define STOT  4097
#define CHF   4
#define NCHF  1025   /* ceil(4097/4) */
#define ROWB  16384  /* DM * 4 bytes */
#define NBUF  8

// -------------------- device scratch --------------------
__device__ float g_Cq[BB * DM];
__device__ float g_Qc[BB * DM];
__device__ float g_Qr[BB * DM];
__device__ float g_u [BB * LD];
__device__ float g_t [BB * DM];
__device__ float g_m [BB * NCHF];
__device__ float g_l [BB * NCHF];
__device__ float g_acc[(size_t)BB * NCHF * DM];   // 67 MB flash partials
__device__ float g_wc[BB * NCHF];
__device__ float g_Linv[BB];
__device__ float g_p [BB * DM];
__device__ float g_a [BB * LD];
__device__ float g_av[BB * DM];

// -------------------- ptx helpers --------------------
__device__ __forceinline__ uint32_t s2u(const void* p) {
    return (uint32_t)__cvta_generic_to_shared(p);
}
#define BAR_INIT(bar, cnt) \
    asm volatile("mbarrier.init.shared.b64 [%0], %1;" :: "r"(bar), "r"(cnt) : "memory")
#define BAR_EXPECT(bar, bytes) \
    asm volatile("mbarrier.arrive.expect_tx.shared.b64 _, [%0], %1;" :: "r"(bar), "r"(bytes) : "memory")
#define BAR_ARRIVE(bar) \
    asm volatile("mbarrier.arrive.shared.b64 _, [%0];" :: "r"(bar) : "memory")
#define BULK_G2S(dst, src, bytes, bar) \
    asm volatile("cp.async.bulk.shared::cluster.global.mbarrier::complete_tx::bytes [%0], [%1], %2, [%3];" \
                 :: "r"(dst), "l"(src), "r"(bytes), "r"(bar) : "memory")
#define FENCE_ASYNC() \
    asm volatile("fence.proxy.async.shared::cta;" ::: "memory")

__device__ __forceinline__ void bar_wait(uint32_t bar, uint32_t parity) {
    asm volatile(
        "{\n\t.reg .pred P;\n"
        "LW_%=:\n\t"
        "mbarrier.try_wait.parity.shared.b64 P, [%0], %1, 0x989680;\n\t"
        "@P bra LD_%=;\n\t"
        "bra LW_%=;\n"
        "LD_%=:\n\t}"
        :: "r"(bar), "r"(parity) : "memory");
}

__device__ __forceinline__ void fma4(float4& a, float s, const float4& v) {
    a.x += s * v.x; a.y += s * v.y; a.z += s * v.z; a.w += s * v.w;
}
__device__ __forceinline__ float dot4(const float4& a, const float4& b) {
    return a.x * b.x + a.y * b.y + a.z * b.z + a.w * b.w;
}

// -------------------- zero atomic targets --------------------
__global__ void k_zero(float* __restrict__ out) {
    int i = blockIdx.x * blockDim.x + threadIdx.x;
    int stride = gridDim.x * blockDim.x;
    for (int j = i; j < BB * DM; j += stride) {
        g_Cq[j] = 0.f; g_Qc[j] = 0.f; g_Qr[j] = 0.f;
        g_av[j] = 0.f; g_p[j] = 0.f; out[j] = 0.f;
    }
    for (int j = i; j < BB * LD; j += stride) g_a[j] = 0.f;
}

// ==================== bulk-pipelined forward gemv ====================
// Y[b][:] += X[b][:] @ W  (W row-major [DM][DM]); smem = 8*16KB ring + x + bars
__global__ __launch_bounds__(256) void k_fw(
    const float* __restrict__ X,
    const float* __restrict__ W0, const float* __restrict__ W1,
    float* __restrict__ Y0, float* __restrict__ Y1)
{
    const float* W = blockIdx.y ? W1 : W0;
    float*       Y = blockIdx.y ? Y1 : Y0;
    extern __shared__ __align__(16) unsigned char sm[];
    float4* bufs = (float4*)sm;                       // NBUF * 1024 float4
    float*  sxv  = (float*)(sm + NBUF * ROWB);        // [BB][32]
    uint32_t sbase = s2u(sm);
    uint32_t bfull = sbase + NBUF * ROWB + 512;
    uint32_t bempt = bfull + 64;
    int tid = threadIdx.x;

    int r0 = (int)(((long long)blockIdx.x * DM) / gridDim.x);
    int r1 = (int)(((long long)(blockIdx.x + 1) * DM) / gridDim.x);
    int R  = r1 - r0;

    if (tid == 0) {
        #pragma unroll
        for (int i = 0; i < NBUF; i++) { BAR_INIT(bfull + i * 8, 1); BAR_INIT(bempt + i * 8, 256); }
    }
    for (int i = tid; i < BB * R; i += 256) {
        int bb = i / R, rr = i - bb * R;
        sxv[bb * 32 + rr] = X[bb * DM + r0 + rr];
    }
    __syncthreads();
    FENCE_ASYNC();

    if (tid == 0) {
        int np = R < NBUF ? R : NBUF;
        for (int i = 0; i < np; i++) {
            BAR_EXPECT(bfull + i * 8, ROWB);
            BULK_G2S(sbase + i * ROWB, W + (size_t)(r0 + i) * DM, ROWB, bfull + i * 8);
        }
    }

    float4 a0[4] = {{0,0,0,0},{0,0,0,0},{0,0,0,0},{0,0,0,0}};
    float4 a1[4] = {{0,0,0,0},{0,0,0,0},{0,0,0,0},{0,0,0,0}};
    float4 a2[4] = {{0,0,0,0},{0,0,0,0},{0,0,0,0},{0,0,0,0}};
    float4 a3[4] = {{0,0,0,0},{0,0,0,0},{0,0,0,0},{0,0,0,0}};

    for (int rr = 0; rr < R; rr++) {
        int buf = rr & (NBUF - 1);
        uint32_t ph = (rr >> 3) & 1;
        bar_wait(bfull + buf * 8, ph);
        float x0 = sxv[0 * 32 + rr], x1 = sxv[1 * 32 + rr];
        float x2 = sxv[2 * 32 + rr], x3 = sxv[3 * 32 + rr];
        #pragma unroll
        for (int s = 0; s < 4; s++) {
            float4 wv = bufs[buf * 1024 + tid + 256 * s];
            fma4(a0[s], x0, wv); fma4(a1[s], x1, wv);
            fma4(a2[s], x2, wv); fma4(a3[s], x3, wv);
        }
        BAR_ARRIVE(bempt + buf * 8);
        if (tid == 0 && rr + NBUF < R) {
            bar_wait(bempt + buf * 8, ph);
            BAR_EXPECT(bfull + buf * 8, ROWB);
            BULK_G2S(sbase + buf * ROWB, W + (size_t)(r0 + rr + NBUF) * DM, ROWB, bfull + buf * 8);
        }
    }

    #pragma unroll
    for (int s = 0; s < 4; s++) {
        int j = (tid + 256 * s) * 4;
        atomicAdd(&Y[0 * DM + j + 0], a0[s].x); atomicAdd(&Y[0 * DM + j + 1], a0[s].y);
        atomicAdd(&Y[0 * DM + j + 2], a0[s].z); atomicAdd(&Y[0 * DM + j + 3], a0[s].w);
        atomicAdd(&Y[1 * DM + j + 0], a1[s].x); atomicAdd(&Y[1 * DM + j + 1], a1[s].y);
        atomicAdd(&Y[1 * DM + j + 2], a1[s].z); atomicAdd(&Y[1 * DM + j + 3], a1[s].w);
        atomicAdd(&Y[2 * DM + j + 0], a2[s].x); atomicAdd(&Y[2 * DM + j + 1], a2[s].y);
        atomicAdd(&Y[2 * DM + j + 2], a2[s].z); atomicAdd(&Y[2 * DM + j + 3], a2[s].w);
        atomicAdd(&Y[3 * DM + j + 0], a3[s].x); atomicAdd(&Y[3 * DM + j + 1], a3[s].y);
        atomicAdd(&Y[3 * DM + j + 2], a3[s].z); atomicAdd(&Y[3 * DM + j + 3], a3[s].w);
    }
}

// ==================== bulk-pipelined transposed gemv ====================
// Y[b][r] = dot(W[r][0:DM], Q[b][:]); W row stride ldw (floats); no atomics.
__global__ __launch_bounds__(256) void k_tr(
    const float* __restrict__ Q,
    const float* __restrict__ W, size_t ldw,
    float* __restrict__ Y, int ystride, int rows)
{
    extern __shared__ __align__(16) unsigned char sm[];
    float4* bufs = (float4*)sm;
    float*  sred = (float*)(sm + NBUF * ROWB);        // [2][8][4]
    uint32_t sbase = s2u(sm);
    uint32_t bfull = sbase + NBUF * ROWB + 256;
    uint32_t bempt = bfull + 64;
    int tid  = threadIdx.x;
    int wid  = tid >> 5;
    int lane = tid & 31;

    int r0 = (int)(((long long)blockIdx.x * rows) / gridDim.x);
    int r1 = (int)(((long long)(blockIdx.x + 1) * rows) / gridDim.x);
    int R  = r1 - r0;

    if (tid == 0) {
        #pragma unroll
        for (int i = 0; i < NBUF; i++) { BAR_INIT(bfull + i * 8, 1); BAR_INIT(bempt + i * 8, 256); }
    }
    __syncthreads();
    FENCE_ASYNC();
    if (tid == 0) {
        int np = R < NBUF ? R : NBUF;
        for (int i = 0; i < np; i++) {
            BAR_EXPECT(bfull + i * 8, ROWB);
            BULK_G2S(sbase + i * ROWB, W + (size_t)(r0 + i) * ldw, ROWB, bfull + i * 8);
        }
    }

    const float4* Q4 = (const float4*)Q;
    float4 q[BB][4];
    #pragma unroll
    for (int b = 0; b < BB; b++)
        #pragma unroll
        for (int s = 0; s < 4; s++)
            q[b][s] = Q4[b * 1024 + tid + 256 * s];

    for (int rr = 0; rr < R; rr++) {
        int buf = rr & (NBUF - 1);
        uint32_t ph = (rr >> 3) & 1;
        bar_wait(bfull + buf * 8, ph);
        float p0 = 0.f, p1 = 0.f, p2 = 0.f, p3 = 0.f;
        #pragma unroll
        for (int s = 0; s < 4; s++) {
            float4 wv = bufs[buf * 1024 + tid + 256 * s];
            p0 += dot4(wv, q[0][s]); p1 += dot4(wv, q[1][s]);
            p2 += dot4(wv, q[2][s]); p3 += dot4(wv, q[3][s]);
        }
        BAR_ARRIVE(bempt + buf * 8);
        if (tid == 0 && rr + NBUF < R) {
            bar_wait(bempt + buf * 8, ph);
            BAR_EXPECT(bfull + buf * 8, ROWB);
            BULK_G2S(sbase + buf * ROWB, W + (size_t)(r0 + rr + NBUF) * ldw, ROWB, bfull + buf * 8);
        }
        #pragma unroll
        for (int o = 16; o > 0; o >>= 1) {
            p0 += __shfl_xor_sync(0xffffffffu, p0, o);
            p1 += __shfl_xor_sync(0xffffffffu, p1, o);
            p2 += __shfl_xor_sync(0xffffffffu, p2, o);
            p3 += __shfl_xor_sync(0xffffffffu, p3, o);
        }
        int slot = (rr & 1) * 32 + wid * 4;
        if (lane == 0) { sred[slot+0]=p0; sred[slot+1]=p1; sred[slot+2]=p2; sred[slot+3]=p3; }
        __syncthreads();
        if (tid < BB) {
            float v = 0.f;
            #pragma unroll
            for (int w = 0; w < 8; w++) v += sred[(rr & 1) * 32 + w * 4 + tid];
            Y[tid * ystride + r0 + rr] = v;
        }
    }
}

// ==================== flash: smem-resident chunk of 4 rows ====================
__global__ __launch_bounds__(256) void k_flash(
    const float* __restrict__ x, const float* __restrict__ past)
{
    int b    = blockIdx.y;
    int c    = blockIdx.x;
    int tid  = threadIdx.x;
    int wid  = tid >> 5;
    int lane = tid & 31;
    extern __shared__ __align__(16) unsigned char sm[];
    float4* bufs = (float4*)sm;                    // CHF * 1024 float4
    float*  sred = (float*)(sm + CHF * ROWB);      // [CHF][8]
    uint32_t sbase = s2u(sm);
    uint32_t bar = sbase + CHF * ROWB + 128;

    int s0 = c * CHF;
    int nv = STOT - s0; if (nv > CHF) nv = CHF;

    if (tid == 0) BAR_INIT(bar, 1);
    __syncthreads();
    FENCE_ASYNC();
    if (tid == 0) {
        BAR_EXPECT(bar, (uint32_t)(nv * ROWB));
        for (int i = 0; i < nv; i++) {
            int s = s0 + i;
            const float* src = (s < SP) ? past + ((size_t)b * SP + s) * DM
                                        : x + (size_t)b * DM;
            BULK_G2S(sbase + i * ROWB, src, ROWB, bar);
        }
    }

    const float4* t4 = (const float4*)(g_t + (size_t)b * DM);
    float4 tv[4];
    #pragma unroll
    for (int s = 0; s < 4; s++) tv[s] = t4[tid + 256 * s];

    bar_wait(bar, 0);

    for (int i = 0; i < nv; i++) {
        float p = 0.f;
        #pragma unroll
        for (int s = 0; s < 4; s++)
            p += dot4(bufs[i * 1024 + tid + 256 * s], tv[s]);
        #pragma unroll
        for (int o = 16; o > 0; o >>= 1) p += __shfl_xor_sync(0xffffffffu, p, o);
        if (lane == 0) sred[i * 8 + wid] = p;
    }
    __syncthreads();

    float m = -INFINITY;
    float sc[CHF];
    for (int i = 0; i < nv; i++) {
        float s = 0.f;
        #pragma unroll
        for (int w = 0; w < 8; w++) s += sred[i * 8 + w];
        sc[i] = s;
        m = fmaxf(m, s);
    }
    float e[CHF], l = 0.f;
    #pragma unroll
    for (int i = 0; i < CHF; i++) {
        e[i] = (i < nv) ? __expf(sc[i] - m) : 0.f;
        l += e[i];
    }

    float4 A[4] = {{0,0,0,0},{0,0,0,0},{0,0,0,0},{0,0,0,0}};
    for (int i = 0; i < nv; i++) {
        #pragma unroll
        for (int s = 0; s < 4; s++)
            fma4(A[s], e[i], bufs[i * 1024 + tid + 256 * s]);
    }

    float4* acc4 = (float4*)(g_acc + ((size_t)b * NCHF + c) * DM);
    #pragma unroll
    for (int s = 0; s < 4; s++) acc4[tid + 256 * s] = A[s];
    if (tid == 0) { g_m[b * NCHF + c] = m; g_l[b * NCHF + c] = l; }
}

// ==================== softmax stats across chunks ====================
__global__ __launch_bounds__(256) void k_stats() {
    int b = blockIdx.x;
    int tid = threadIdx.x;
    __shared__ float sr[8];
    __shared__ float sM;

    float m = -INFINITY;
    for (int c = tid; c < NCHF; c += 256) m = fmaxf(m, g_m[b * NCHF + c]);
    #pragma unroll
    for (int o = 16; o > 0; o >>= 1) m = fmaxf(m, __shfl_xor_sync(0xffffffffu, m, o));
    if ((tid & 31) == 0) sr[tid >> 5] = m;
    __syncthreads();
    if (tid < 8) {
        float v = sr[tid];
        #pragma unroll
        for (int o = 4; o > 0; o >>= 1) v = fmaxf(v, __shfl_xor_sync(0xffu, v, o));
        if (tid == 0) sM = v;
    }
    __syncthreads();
    float M = sM;
    __syncthreads();

    float lsum = 0.f;
    for (int c = tid; c < NCHF; c += 256) {
        float w = __expf(g_m[b * NCHF + c] - M);
        g_wc[b * NCHF + c] = w;
        lsum += w * g_l[b * NCHF + c];
    }
    #pragma unroll
    for (int o = 16; o > 0; o >>= 1) lsum += __shfl_xor_sync(0xffffffffu, lsum, o);
    if ((tid & 31) == 0) sr[tid >> 5] = lsum;
    __syncthreads();
    if (tid == 0) {
        float L = 0.f;
        #pragma unroll
        for (int w = 0; w < 8; w++) L += sr[w];
        g_Linv[b] = 1.f / L;
    }
}

// ==================== combine partials (unscaled; 1/L folded later) ========
__global__ __launch_bounds__(256) void k_combine() {
    int b = blockIdx.y;
    int d = blockIdx.x * 256 + threadIdx.x;
    int c0 = (int)(((long long)blockIdx.z * NCHF) / gridDim.z);
    int c1 = (int)(((long long)(blockIdx.z + 1) * NCHF) / gridDim.z);
    const float* accp = g_acc + (size_t)b * NCHF * DM + d;
    const float* wcp  = g_wc + b * NCHF;
    float s = 0.f;
    #pragma unroll 4
    for (int c = c0; c < c1; c++) s += wcp[c] * accp[(size_t)c * DM];
    atomicAdd(&g_p[b * DM + d], s);
}

// ==================== small forward gemv ====================
__global__ __launch_bounds__(256) void k_gemv4(
    const float* __restrict__ X, int xstride, const float* __restrict__ xscale,
    const float* __restrict__ W, int ldw,
    float* __restrict__ Y, int ystride,
    int K, int N, int kchunk)
{
    const int N4 = N >> 2;
    const int ldw4 = ldw >> 2;
    int tid = threadIdx.x;
    int j4  = blockIdx.x * blockDim.x + tid;
    int d0  = blockIdx.y * kchunk;
    int d1  = min(K, d0 + kchunk);
    int nk  = d1 - d0;

    __shared__ float sx[BB][64];
    for (int i = tid; i < BB * nk; i += blockDim.x) {
        int bb = i / nk, kk = i - bb * nk;
        float v = X[bb * xstride + d0 + kk];
        sx[bb][kk] = xscale ? v * xscale[bb] : v;
    }
    __syncthreads();
    if (j4 >= N4) return;

    const float4* W4 = (const float4*)W;
    float4 a0 = {0,0,0,0}, a1 = a0, a2 = a0, a3 = a0;

    int k = 0;
    for (; k + 16 <= nk; k += 16) {
        float4 wv[16];
        #pragma unroll
        for (int i = 0; i < 16; i++)
            wv[i] = W4[(size_t)(d0 + k + i) * ldw4 + j4];
        #pragma unroll
        for (int i = 0; i < 16; i++) {
            fma4(a0, sx[0][k + i], wv[i]); fma4(a1, sx[1][k + i], wv[i]);
            fma4(a2, sx[2][k + i], wv[i]); fma4(a3, sx[3][k + i], wv[i]);
        }
    }
    for (; k < nk; k++) {
        float4 wv = W4[(size_t)(d0 + k) * ldw4 + j4];
        fma4(a0, sx[0][k], wv); fma4(a1, sx[1][k], wv);
        fma4(a2, sx[2][k], wv); fma4(a3, sx[3][k], wv);
    }

    int j = j4 * 4;
    atomicAdd(&Y[0 * ystride + j + 0], a0.x); atomicAdd(&Y[0 * ystride + j + 1], a0.y);
    atomicAdd(&Y[0 * ystride + j + 2], a0.z); atomicAdd(&Y[0 * ystride + j + 3], a0.w);
    atomicAdd(&Y[1 * ystride + j + 0], a1.x); atomicAdd(&Y[1 * ystride + j + 1], a1.y);
    atomicAdd(&Y[1 * ystride + j + 2], a1.z); atomicAdd(&Y[1 * ystride + j + 3], a1.w);
    atomicAdd(&Y[2 * ystride + j + 0], a2.x); atomicAdd(&Y[2 * ystride + j + 1], a2.y);
    atomicAdd(&Y[2 * ystride + j + 2], a2.z); atomicAdd(&Y[2 * ystride + j + 3], a2.w);
    atomicAdd(&Y[3 * ystride + j + 0], a3.x); atomicAdd(&Y[3 * ystride + j + 1], a3.y);
    atomicAdd(&Y[3 * ystride + j + 2], a3.z); atomicAdd(&Y[3 * ystride + j + 3], a3.w);
}

// ==================== small transposed gemv (step 7) ==============
__global__ __launch_bounds__(256) void k_gemv_t_s(
    const float* __restrict__ X, int xstride,
    const float* __restrict__ W, int ldw,
    float* __restrict__ Y, int ystride,
    int rows, int cols, float scalev)
{
    int gw   = (blockIdx.x * blockDim.x + threadIdx.x) >> 5;
    int lane = threadIdx.x & 31;
    if (gw >= rows) return;
    const float4* wp = (const float4*)(W + (size_t)gw * ldw);
    const float4* X4 = (const float4*)X;
    int cols4 = cols >> 2;
    int x4s   = xstride >> 2;

    float s0 = 0.f, s1 = 0.f, s2 = 0.f, s3 = 0.f;
    for (int c4 = lane; c4 < cols4; c4 += 32) {
        float4 wv = __ldg(&wp[c4]);
        s0 += dot4(wv, __ldg(&X4[0 * x4s + c4]));
        s1 += dot4(wv, __ldg(&X4[1 * x4s + c4]));
        s2 += dot4(wv, __ldg(&X4[2 * x4s + c4]));
        s3 += dot4(wv, __ldg(&X4[3 * x4s + c4]));
    }
    #pragma unroll
    for (int o = 16; o > 0; o >>= 1) {
        s0 += __shfl_xor_sync(0xffffffffu, s0, o);
        s1 += __shfl_xor_sync(0xffffffffu, s1, o);
        s2 += __shfl_xor_sync(0xffffffffu, s2, o);
        s3 += __shfl_xor_sync(0xffffffffu, s3, o);
    }
    if (lane == 0) {
        Y[0 * ystride + gw] = scalev * (Y[0 * ystride + gw] + s0);
        Y[1 * ystride + gw] = scalev * (Y[1 * ystride + gw] + s1);
        Y[2 * ystride + gw] = scalev * (Y[2 * ystride + gw] + s2);
        Y[3 * ystride + gw] = scalev * (Y[3 * ystride + gw] + s3);
    }
}

// ----------------------------------------------------------------------------
extern "C" void kernel_launch(void* const* d_in, const int* in_sizes, int n_in,
                              void* d_out, int out_size)
{
    const float* x    = (const float*)d_in[0];
    const float* past = (const float*)d_in[1];
    const float* Wdq  = (const float*)d_in[2];
    const float* Wuq  = (const float*)d_in[3];
    const float* Wqr  = (const float*)d_in[4];
    const float* Wdkv = (const float*)d_in[5];
    const float* Wkr  = (const float*)d_in[6];
    const float* F    = (const float*)d_in[7];
    const float* Wo   = (const float*)d_in[8];
    float* out = (float*)d_out;

    const float scale = 1.0f / sqrtf(2.0f * (float)DM);

    float *pCq, *pQc, *pQr, *pu, *pt, *pp, *pa, *pav, *pLinv;
    cudaGetSymbolAddress((void**)&pCq, g_Cq);
    cudaGetSymbolAddress((void**)&pQc, g_Qc);
    cudaGetSymbolAddress((void**)&pQr, g_Qr);
    cudaGetSymbolAddress((void**)&pu,  g_u);
    cudaGetSymbolAddress((void**)&pt,  g_t);
    cudaGetSymbolAddress((void**)&pp,  g_p);
    cudaGetSymbolAddress((void**)&pa,  g_a);
    cudaGetSymbolAddress((void**)&pav, g_av);
    cudaGetSymbolAddress((void**)&pLinv, g_Linv);

    const int FW_SMEM = NBUF * ROWB + 512 + 128;
    const int TR_SMEM = NBUF * ROWB + 256 + 128;
    const int FL_SMEM = CHF * ROWB + 128 + 16;
    cudaFuncSetAttribute(k_fw,    cudaFuncAttributeMaxDynamicSharedMemorySize, FW_SMEM);
    cudaFuncSetAttribute(k_tr,    cudaFuncAttributeMaxDynamicSharedMemorySize, TR_SMEM);
    cudaFuncSetAttribute(k_flash, cudaFuncAttributeMaxDynamicSharedMemorySize, FL_SMEM);

    // 1) zero atomic targets
    k_zero<<<128, 256>>>(out);

    // 2) Cq = x @ Wdq                   (64 MB, bulk pipeline)
    k_fw<<<dim3(148, 1), 256, FW_SMEM>>>(x, Wdq, Wdq, pCq, pCq);
    // 3+4) Qc = Cq @ Wuq ; Qr = Cq @ Wqr (128 MB, merged)
    k_fw<<<dim3(148, 2), 256, FW_SMEM>>>(pCq, Wuq, Wqr, pQc, pQr);
    // 5) t = Wkr @ Qr                   (64 MB, bulk transposed)
    k_tr<<<148, 256, TR_SMEM>>>(pQr, Wkr, (size_t)DM, pt, DM, DM);
    // 6) u = F[:, :DM] @ Qc             (8 MB)
    k_tr<<<148, 256, TR_SMEM>>>(pQc, F, (size_t)(2 * DM), pu, LD, LD);
    // 7) t = scale * (t + Wdkv @ u)     (8 MB)
    k_gemv_t_s<<<512, 256>>>(pu, LD, Wdkv, LD, pt, DM, DM, LD, scale);

    // 8) flash pass over [past_x; x]    (268 MB, smem-resident chunks)
    k_flash<<<dim3(NCHF, BB), 256, FL_SMEM>>>(x, past);
    // 9) stats -> g_wc, g_Linv
    k_stats<<<BB, 256>>>();
    // 10) combine partials -> g_p (unscaled)
    k_combine<<<dim3(16, BB, 8), 256>>>();

    // 11) a = (p * Linv) @ Wdkv         (8 MB)
    k_gemv4<<<dim3(1, 64), 256>>>(pp, DM, pLinv, Wdkv, LD, pa, LD, DM, LD, 64);
    // 12) attn_v = a @ F[:, DM:]        (8 MB)
    k_gemv4<<<dim3(4, 8), 256>>>(pa, LD, (const float*)nullptr, F + DM, 2 * DM, pav, DM, LD, DM, 64);
    // 13) out = attn_v @ Wo             (64 MB, bulk pipeline)
    k_fw<<<dim3(148, 1), 256, FW_SMEM>>>(pav, Wo, Wo, out, out);
}